// round 14
// baseline (speedup 1.0000x reference)
#include <cuda_runtime.h>
#include <cuda_fp16.h>
#include <math.h>
#include <stdint.h>

#define BS 16
#define TT 1024
#define T2 2048
#define FD 512
#define ALPHA 0.1f
#define KC 64
#define NCHUNK (T2 / KC)   // 32
#define MI 256
#define NF 128

typedef unsigned long long u64;
typedef unsigned int u32;

// ---------------- device scratch (no cudaMalloc allowed) --------------------
static __device__ __half g_B[(size_t)BS * T2 * FD];        // Wh fp16 [b][j][f]
static __device__ __half g_P[(size_t)BS * T2 * T2];        // P fp16 [b][i][j], 128MB
static __device__ float g_Z[BS * T2];                      // softmax denominators
static __device__ u32 g_adjm[(size_t)BS * T2 * (T2 / 32)]; // adj bitmask
static __device__ uint4 g_tbl[(size_t)BS * (T2 / 2)];      // {w2h2,E1h2,Eah2,0}/2j
static __device__ float g_uvec[2 * FD];
static __device__ float g_w1[BS * T2];
static __device__ float g_w2[BS * T2];
static __device__ float g_F1[BS * T2];
static __device__ float g_Fa[BS * T2];

// ---------------- helpers ----------------------------------------------------
__device__ __forceinline__ u32 packhf(float lo, float hi) {
    u32 r; asm("cvt.rn.f16x2.f32 %0, %1, %2;" : "=r"(r) : "f"(hi), "f"(lo)); return r;
}
__device__ __forceinline__ u32 hadd2u(u32 a, u32 b) {
    u32 d; asm("add.rn.f16x2 %0, %1, %2;" : "=r"(d) : "r"(a), "r"(b)); return d;
}
__device__ __forceinline__ u32 hmul2u(u32 a, u32 b) {
    u32 d; asm("mul.rn.f16x2 %0, %1, %2;" : "=r"(d) : "r"(a), "r"(b)); return d;
}
__device__ __forceinline__ u32 hsetgt2(u32 a, u32 b) {
    u32 d; asm("set.gt.u32.f16x2 %0, %1, %2;" : "=r"(d) : "r"(a), "r"(b)); return d;
}
// (a & c) | (b & ~c)
__device__ __forceinline__ u32 lop3e4(u32 a, u32 b, u32 c) {
    u32 d; asm("lop3.b32 %0, %1, %2, %3, 0xE4;" : "=r"(d) : "r"(a), "r"(b), "r"(c));
    return d;
}
__device__ __forceinline__ u32 smem_u32(const void* p) {
    u32 a; asm("{ .reg .u64 t; cvta.to.shared.u64 t, %1; cvt.u32.u64 %0, t; }"
               : "=r"(a) : "l"(p));
    return a;
}
__device__ __forceinline__ void ldsm_x4(u32* r, u32 addr) {
    asm volatile("ldmatrix.sync.aligned.m8n8.x4.shared.b16 {%0,%1,%2,%3}, [%4];"
                 : "=r"(r[0]), "=r"(r[1]), "=r"(r[2]), "=r"(r[3]) : "r"(addr));
}
__device__ __forceinline__ void ldsm_x4t(u32* r, u32 addr) {
    asm volatile("ldmatrix.sync.aligned.m8n8.x4.trans.shared.b16 {%0,%1,%2,%3}, [%4];"
                 : "=r"(r[0]), "=r"(r[1]), "=r"(r[2]), "=r"(r[3]) : "r"(addr));
}
__device__ __forceinline__ void mma_f16(float* d, const u32* a, u32 b0, u32 b1) {
    asm volatile(
        "mma.sync.aligned.m16n8k16.row.col.f32.f16.f16.f32 "
        "{%0,%1,%2,%3}, {%4,%5,%6,%7}, {%8,%9}, {%0,%1,%2,%3};"
        : "+f"(d[0]), "+f"(d[1]), "+f"(d[2]), "+f"(d[3])
        : "r"(a[0]), "r"(a[1]), "r"(a[2]), "r"(a[3]), "r"(b0), "r"(b1));
}
__device__ __forceinline__ void cpa16(u32 dst, const void* src) {
    asm volatile("{ .reg .u64 g; cvta.to.global.u64 g, %1; "
                 "cp.async.cg.shared.global [%0], [g], 16; }"
                 :: "r"(dst), "l"(src) : "memory");
}

// ---------------------------------------------------------------------------
// k_pack: adj (int32) -> bitmask.
// ---------------------------------------------------------------------------
__global__ __launch_bounds__(256) void k_pack(const int* __restrict__ adj) {
    size_t o = (size_t)blockIdx.x * 256 + threadIdx.x;
    const int* src = adj + o * 32;
    u32 m = 0;
    #pragma unroll
    for (int q = 0; q < 8; q++) {
        int4 v = *(const int4*)(src + q * 4);
        m |= (v.x > 0 ? 1u : 0u) << (q * 4);
        m |= (v.y > 0 ? 1u : 0u) << (q * 4 + 1);
        m |= (v.z > 0 ? 1u : 0u) << (q * 4 + 2);
        m |= (v.w > 0 ? 1u : 0u) << (q * 4 + 3);
    }
    g_adjm[o] = m;
}

// ---------------------------------------------------------------------------
// k_u: u1 = W @ a1, u2 = W @ a2.
// ---------------------------------------------------------------------------
__global__ __launch_bounds__(256) void k_u(const float* __restrict__ W,
                                           const float* __restrict__ avec) {
    int k = blockIdx.x * 8 + (threadIdx.x >> 5);
    int lane = threadIdx.x & 31;
    const float* wr = W + (size_t)k * FD;
    float s1 = 0.f, s2 = 0.f;
    #pragma unroll
    for (int q = 0; q < 4; q++) {
        int f4 = lane + 32 * q;
        float4 w = *(const float4*)&wr[f4 * 4];
        float4 a1 = *(const float4*)&avec[f4 * 4];
        float4 a2 = *(const float4*)&avec[FD + f4 * 4];
        s1 += w.x * a1.x + w.y * a1.y + w.z * a1.z + w.w * a1.w;
        s2 += w.x * a2.x + w.y * a2.y + w.z * a2.z + w.w * a2.w;
    }
    #pragma unroll
    for (int o = 16; o > 0; o >>= 1) {
        s1 += __shfl_xor_sync(0xffffffffu, s1, o);
        s2 += __shfl_xor_sync(0xffffffffu, s2, o);
    }
    if (lane == 0) { g_uvec[k] = s1; g_uvec[FD + k] = s2; }
}

// ---------------------------------------------------------------------------
// k_w12: w1/w2 exact fp32 via associativity.
// ---------------------------------------------------------------------------
__global__ __launch_bounds__(256) void k_w12(const float* __restrict__ xa,
                                             const float* __restrict__ xv) {
    int row  = blockIdx.x * 8 + (threadIdx.x >> 5);
    int lane = threadIdx.x & 31;
    int b = row >> 11, r = row & (T2 - 1);
    const float* h = (r < TT) ? xa + ((size_t)b * TT + r) * FD
                              : xv + ((size_t)b * TT + (r - TT)) * FD;
    float s1 = 0.f, s2 = 0.f;
    #pragma unroll
    for (int q = 0; q < 4; q++) {
        int f4 = lane + 32 * q;
        float4 v  = *(const float4*)&h[f4 * 4];
        float4 a1 = *(const float4*)&g_uvec[f4 * 4];
        float4 a2 = *(const float4*)&g_uvec[FD + f4 * 4];
        s1 += v.x * a1.x + v.y * a1.y + v.z * a1.z + v.w * a1.w;
        s2 += v.x * a2.x + v.y * a2.y + v.z * a2.z + v.w * a2.w;
    }
    #pragma unroll
    for (int o = 16; o > 0; o >>= 1) {
        s1 += __shfl_xor_sync(0xffffffffu, s1, o);
        s2 += __shfl_xor_sync(0xffffffffu, s2, o);
    }
    if (lane == 0) { g_w1[row] = s1; g_w2[row] = s2; }
}

// ---------------------------------------------------------------------------
// k_prep: max-shifted fp16 tables (all values <= 1, overflow-safe).
// ---------------------------------------------------------------------------
__global__ __launch_bounds__(256) void k_prep() {
    __shared__ float red[256];
    __shared__ float Msh;
    int b = blockIdx.x, tid = threadIdx.x;
    const float* w2 = g_w2 + b * T2;
    float m = -1e30f;
    for (int i = tid; i < T2; i += 256) m = fmaxf(m, w2[i]);
    red[tid] = m; __syncthreads();
    for (int s = 128; s > 0; s >>= 1) {
        if (tid < s) red[tid] = fmaxf(red[tid], red[tid + s]);
        __syncthreads();
    }
    if (tid == 0) Msh = red[0];
    __syncthreads();
    float M = Msh;
    for (int j2 = tid; j2 < T2 / 2; j2 += 256) {
        int j = 2 * j2;
        float w2a = w2[j], w2b = w2[j + 1];
        float e1a = expf(w2a - M), e1b = expf(w2b - M);
        float eaa = expf(ALPHA * (w2a - M)), eab = expf(ALPHA * (w2b - M));
        g_tbl[(size_t)b * (T2 / 2) + j2] =
            make_uint4(packhf(w2a, w2b), packhf(e1a, e1b), packhf(eaa, eab), 0);
    }
    const float* w1 = g_w1 + b * T2;
    for (int i = tid; i < T2; i += 256) {
        float v1 = w1[i];
        float s  = v1 + M;
        float mi = s > 0.f ? s : ALPHA * s;
        g_F1[b * T2 + i] = expf(s - mi);
        g_Fa[b * T2 + i] = expf(ALPHA * s - mi);
    }
}

// ---------------------------------------------------------------------------
// k_p: materialize P fp16 [b][i][j] + exact fp32 row sums Z. Block = one row.
// ---------------------------------------------------------------------------
__global__ __launch_bounds__(256) void k_p() {
    __shared__ float red[8];
    const int row = blockIdx.x;          // b*T2 + i
    const int b = row >> 11;
    const int t = threadIdx.x;
    const int lane = t & 31, wid = t >> 5;

    const float w1f = g_w1[row];
    const float f1f = g_F1[row], faf = g_Fa[row];
    const u32 w1h2 = packhf(w1f, w1f);
    const u32 F1h2 = packhf(f1f, f1f);
    const u32 Fah2 = packhf(faf, faf);

    u32 mw = g_adjm[(size_t)row * (T2 / 32) + (t >> 2)];
    u32 mbits = (mw >> ((t & 3) * 8)) & 0xFFu;
    const uint4* tb = g_tbl + (size_t)b * (T2 / 2) + t * 4;

    u32 hw[4];
    float zs = 0.f;
    #pragma unroll
    for (int e2 = 0; e2 < 4; e2++) {
        uint4 tt = tb[e2];
        u32 s = hadd2u(w1h2, tt.x);
        u32 m = hsetgt2(s, 0u);
        u32 e = lop3e4(tt.y, tt.z, m);
        u32 f = lop3e4(F1h2, Fah2, m);
        u32 p = hmul2u(f, e);
        u32 am = (((mbits >> (e2 * 2)) & 1u) * 0xFFFFu)
               | (((mbits >> (e2 * 2 + 1)) & 1u) * 0xFFFF0000u);
        p &= am;
        hw[e2] = p;
        float2 pf = __half22float2(*reinterpret_cast<__half2*>(&p));
        zs += pf.x + pf.y;
    }
    *(uint4*)&g_P[(size_t)row * T2 + t * 8] = make_uint4(hw[0], hw[1], hw[2], hw[3]);

    #pragma unroll
    for (int o = 16; o > 0; o >>= 1) zs += __shfl_xor_sync(0xffffffffu, zs, o);
    if (lane == 0) red[wid] = zs;
    __syncthreads();
    if (t == 0) {
        float z = 0.f;
        #pragma unroll
        for (int w = 0; w < 8; w++) z += red[w];
        g_Z[row] = z;
    }
}

// ---------------------------------------------------------------------------
// k_wh_mma: Wh = fl16(h) @ fl16(W), single fp16 pass. (validated)
// ---------------------------------------------------------------------------
#define WA_RB 144
#define WW_RB 272
#define SW_A 0
#define SW_W 18432
#define SW_TOTAL 35840

__global__ __launch_bounds__(256, 2) void k_wh_mma(const float* __restrict__ xa,
                                                   const float* __restrict__ xv,
                                                   const float* __restrict__ W) {
    extern __shared__ char sm[];
    const u32 smb = smem_u32(sm);
    const int tid = threadIdx.x, lane = tid & 31, wid = tid >> 5;
    const int wm = wid & 3, wn = wid >> 2;
    const int b  = blockIdx.z;
    const int r0 = blockIdx.y * 128;
    const int f0 = blockIdx.x * 128;
    const float* __restrict__ h = (r0 < TT)
        ? (xa + ((size_t)b * TT + r0) * FD)
        : (xv + ((size_t)b * TT + (r0 - TT)) * FD);

    float acc[2][8][4];
    #pragma unroll
    for (int m = 0; m < 2; m++)
        #pragma unroll
        for (int n = 0; n < 8; n++)
            #pragma unroll
            for (int e = 0; e < 4; e++) acc[m][n][e] = 0.f;

    const u32 a_lane = (u32)(lane & 15) * WA_RB + (u32)(lane >> 4) * 16;
    const u32 b_lane = (u32)(lane & 15) * WW_RB + (u32)(lane >> 4) * 16;
    const u32 pa = smb + SW_A + (u32)(wm * 32) * WA_RB + a_lane;
    const u32 pb = smb + SW_W + (u32)(wn * 64) * 2 + b_lane;

    for (int k0 = 0; k0 < FD; k0 += KC) {
        if (k0) __syncthreads();
        #pragma unroll
        for (int s = 0; s < 8; s++) {
            int u = tid + 256 * s;
            int row = u >> 4, kq = u & 15;
            float4 v = *(const float4*)(h + (size_t)row * FD + k0 + kq * 4);
            uint2 qh = make_uint2(packhf(v.x, v.y), packhf(v.z, v.w));
            *(uint2*)(sm + SW_A + row * WA_RB + kq * 8) = qh;
        }
        #pragma unroll
        for (int s = 0; s < 8; s++) {
            int u = tid + 256 * s;
            int row = u >> 5, fq = u & 31;
            float4 v = *(const float4*)(W + (size_t)(k0 + row) * FD + f0 + fq * 4);
            uint2 qh = make_uint2(packhf(v.x, v.y), packhf(v.z, v.w));
            *(uint2*)(sm + SW_W + row * WW_RB + fq * 8) = qh;
        }
        __syncthreads();
        #pragma unroll
        for (int kk = 0; kk < 4; kk++) {
            u32 ahi[2][4];
            ldsm_x4(ahi[0], pa + kk * 32);
            ldsm_x4(ahi[1], pa + kk * 32 + 16 * WA_RB);
            #pragma unroll
            for (int nt = 0; nt < 4; nt++) {
                u32 bhv[4];
                ldsm_x4t(bhv, pb + (u32)kk * 16 * WW_RB + (u32)nt * 32);
                #pragma unroll
                for (int mt = 0; mt < 2; mt++) {
                    mma_f16(acc[mt][2 * nt],     ahi[mt], bhv[0], bhv[1]);
                    mma_f16(acc[mt][2 * nt + 1], ahi[mt], bhv[2], bhv[3]);
                }
            }
        }
    }

    #pragma unroll
    for (int mt = 0; mt < 2; mt++) {
        int row1 = r0 + wm * 32 + mt * 16 + (lane >> 2);
        #pragma unroll
        for (int nt2 = 0; nt2 < 8; nt2++) {
            int col = f0 + wn * 64 + nt2 * 8 + (lane & 3) * 2;
            u32 h01 = packhf(acc[mt][nt2][0], acc[mt][nt2][1]);
            u32 h23 = packhf(acc[mt][nt2][2], acc[mt][nt2][3]);
            size_t o1 = ((size_t)b * T2 + row1) * FD + col;
            size_t o2 = o1 + (size_t)8 * FD;
            *(u32*)&g_B[o1] = h01;
            *(u32*)&g_B[o2] = h23;
        }
    }
}

// ---------------------------------------------------------------------------
// k_attn_mma: pure staged GEMM, MI=256 x NF=128 tile, 512 thr (8m x 2n warps),
// 3-deep cp.async pipeline. Higher intensity: 48KB staged per 1024 MMAs.
// ---------------------------------------------------------------------------
#define WHS_RB   272                // 128 f x 2B + 16 pad
#define PS_RB    144                // 64 j x 2B + 16 pad
#define WHS_BUF  17408              // 64 rows x 272
#define PS_BUF   36864              // 256 rows x 144
#define SM_PS    52224              // 3 * WHS_BUF
#define SM_ATTN_TOTAL 162816        // SM_PS + 3*PS_BUF

__device__ __forceinline__ void stage_tiles(u32 smb, int bsel,
                                            const __half* bh, const __half* prow,
                                            int j0, int f0, int tid) {
    u32 wbase = smb + (u32)bsel * WHS_BUF;
    #pragma unroll
    for (int s = 0; s < 2; s++) {
        int u = tid + 512 * s;
        int row = u >> 4, fo = u & 15;
        cpa16(wbase + row * WHS_RB + fo * 16,
              bh + (size_t)(j0 + row) * FD + f0 + fo * 8);
    }
    u32 pbase = smb + SM_PS + (u32)bsel * PS_BUF;
    #pragma unroll
    for (int s = 0; s < 4; s++) {
        int u = tid + 512 * s;
        int row = u >> 3, jo = u & 7;
        cpa16(pbase + row * PS_RB + jo * 16,
              prow + (size_t)row * T2 + j0 + jo * 8);
    }
    asm volatile("cp.async.commit_group;" ::: "memory");
}

__global__ __launch_bounds__(512, 1) void k_attn_mma(float* __restrict__ out) {
    extern __shared__ char sm[];
    const u32 smb = smem_u32(sm);
    const int tid = threadIdx.x;
    const int lane = tid & 31, wid = tid >> 5;
    const int wm = wid & 7, wn = wid >> 3;   // 8 x 2 warp grid
    const int b  = blockIdx.z;
    const int i0 = blockIdx.x * MI;
    const int f0 = blockIdx.y * NF;

    const __half* bhsrc = g_B + (size_t)b * T2 * FD;
    const __half* prow  = g_P + ((size_t)(b * T2 + i0)) * T2;

    stage_tiles(smb, 0, bhsrc, prow, 0, f0, tid);
    stage_tiles(smb, 1, bhsrc, prow, KC, f0, tid);

    float acc[2][8][4];
    #pragma unroll
    for (int m = 0; m < 2; m++)
        #pragma unroll
        for (int n = 0; n < 8; n++)
            #pragma unroll
            for (int e = 0; e < 4; e++) acc[m][n][e] = 0.f;

    const u32 a_lane = (u32)(lane & 15) * PS_RB + (u32)(lane >> 4) * 16;
    const u32 b_lane = (u32)(lane & 15) * WHS_RB + (u32)(lane >> 4) * 16;
    const u32 pa_base = smb + SM_PS + (u32)(wm * 32) * PS_RB + a_lane;

    asm volatile("cp.async.wait_group 1;" ::: "memory");
    __syncthreads();

    for (int c = 0; c < NCHUNK; c++) {
        if (c + 2 < NCHUNK)
            stage_tiles(smb, (c + 2) % 3, bhsrc, prow, (c + 2) * KC, f0, tid);

        const u32 pa = pa_base + (u32)(c % 3) * PS_BUF;
        const u32 wb = smb + (u32)(c % 3) * WHS_BUF + (u32)(wn * 64) * 2 + b_lane;
        #pragma unroll
        for (int kk = 0; kk < 4; kk++) {
            u32 ap_[2][4];
            ldsm_x4(ap_[0], pa + kk * 32);
            ldsm_x4(ap_[1], pa + kk * 32 + 16 * PS_RB);
            #pragma unroll
            for (int nt = 0; nt < 4; nt++) {
                u32 bhv[4];
                ldsm_x4t(bhv, wb + (u32)kk * 16 * WHS_RB + (u32)nt * 32);
                #pragma unroll
                for (int mt = 0; mt < 2; mt++) {
                    mma_f16(acc[mt][2 * nt],     ap_[mt], bhv[0], bhv[1]);
                    mma_f16(acc[mt][2 * nt + 1], ap_[mt], bhv[2], bhv[3]);
                }
            }
        }

        if (c + 2 < NCHUNK)
            asm volatile("cp.async.wait_group 1;" ::: "memory");
        else
            asm volatile("cp.async.wait_group 0;" ::: "memory");
        __syncthreads();
    }

    // epilogue: normalize (Z from g_Z), elu, split-write
    #pragma unroll
    for (int mt = 0; mt < 2; mt++) {
        int il = wm * 32 + mt * 16 + (lane >> 2);
        int g1 = i0 + il, g2 = g1 + 8;
        float inv1 = 1.f / g_Z[b * T2 + g1];
        float inv2 = 1.f / g_Z[b * T2 + g2];
        size_t base1 = (g1 < TT) ? ((size_t)b * TT + g1) * FD
                                 : ((size_t)BS * TT + (size_t)b * TT + (g1 - TT)) * FD;
        size_t base2 = (g2 < TT) ? ((size_t)b * TT + g2) * FD
                                 : ((size_t)BS * TT + (size_t)b * TT + (g2 - TT)) * FD;
        #pragma unroll
        for (int nt = 0; nt < 8; nt++) {
            int col = f0 + wn * 64 + nt * 8 + (lane & 3) * 2;
            float2 v1, v2;
            float x;
            x = acc[mt][nt][0] * inv1; v1.x = x > 0.f ? x : expm1f(x);
            x = acc[mt][nt][1] * inv1; v1.y = x > 0.f ? x : expm1f(x);
            x = acc[mt][nt][2] * inv2; v2.x = x > 0.f ? x : expm1f(x);
            x = acc[mt][nt][3] * inv2; v2.y = x > 0.f ? x : expm1f(x);
            *(float2*)&out[base1 + col] = v1;
            *(float2*)&out[base2 + col] = v2;
        }
    }
}

// ---------------------------------------------------------------------------
extern "C" void kernel_launch(void* const* d_in, const int* in_sizes, int n_in,
                              void* d_out, int out_size) {
    const float* xa  = (const float*)d_in[0];
    const float* xv  = (const float*)d_in[1];
    const int*   adj = (const int*)d_in[2];
    const float* W   = (const float*)d_in[3];
    const float* a   = (const float*)d_in[4];
    float* out = (float*)d_out;

    cudaFuncSetAttribute(k_wh_mma, cudaFuncAttributeMaxDynamicSharedMemorySize,
                         SW_TOTAL);
    cudaFuncSetAttribute(k_attn_mma, cudaFuncAttributeMaxDynamicSharedMemorySize,
                         SM_ATTN_TOTAL);

    k_pack<<<BS * T2 * (T2 / 32) / 256, 256>>>(adj);
    k_u<<<FD / 8, 256>>>(W, a);
    k_w12<<<BS * T2 / 8, 256>>>(xa, xv);
    k_prep<<<BS, 256>>>();
    k_p<<<BS * T2, 256>>>();                 // 32768 blocks, one row each
    dim3 gA(FD / 128, T2 / 128, BS);
    k_wh_mma<<<gA, 256, SW_TOTAL>>>(xa, xv, W);
    dim3 gC(T2 / MI, FD / NF, BS);           // 8 x 4 x 16 = 512 blocks
    k_attn_mma<<<gC, 512, SM_ATTN_TOTAL>>>(out);
}

// round 15
// speedup vs baseline: 1.1983x; 1.1983x over previous
#include <cuda_runtime.h>
#include <cuda_fp16.h>
#include <math.h>
#include <stdint.h>

#define BS 16
#define TT 1024
#define T2 2048
#define FD 512
#define ALPHA 0.1f
#define KC 64
#define NCHUNK (T2 / KC)   // 32
#define MI 128
#define NF 128

typedef unsigned long long u64;
typedef unsigned int u32;

// ---------------- device scratch (no cudaMalloc allowed) --------------------
static __device__ __half g_B[(size_t)BS * T2 * FD];        // Wh fp16 [b][j][f]
static __device__ __half g_P[(size_t)BS * T2 * T2];        // P fp16 [b][i][j], 128MB
static __device__ float g_Z[BS * T2];                      // softmax denominators
static __device__ uint4 g_tbl[(size_t)BS * (T2 / 2)];      // {w2h2,E1h2,Eah2,0}/2j
static __device__ float g_uvec[2 * FD];
static __device__ float g_w1[BS * T2];
static __device__ float g_w2[BS * T2];
static __device__ float g_F1[BS * T2];
static __device__ float g_Fa[BS * T2];

// ---------------- helpers ----------------------------------------------------
__device__ __forceinline__ u32 packhf(float lo, float hi) {
    u32 r; asm("cvt.rn.f16x2.f32 %0, %1, %2;" : "=r"(r) : "f"(hi), "f"(lo)); return r;
}
__device__ __forceinline__ u32 hadd2u(u32 a, u32 b) {
    u32 d; asm("add.rn.f16x2 %0, %1, %2;" : "=r"(d) : "r"(a), "r"(b)); return d;
}
__device__ __forceinline__ u32 hmul2u(u32 a, u32 b) {
    u32 d; asm("mul.rn.f16x2 %0, %1, %2;" : "=r"(d) : "r"(a), "r"(b)); return d;
}
__device__ __forceinline__ u32 hsetgt2(u32 a, u32 b) {
    u32 d; asm("set.gt.u32.f16x2 %0, %1, %2;" : "=r"(d) : "r"(a), "r"(b)); return d;
}
// (a & c) | (b & ~c)
__device__ __forceinline__ u32 lop3e4(u32 a, u32 b, u32 c) {
    u32 d; asm("lop3.b32 %0, %1, %2, %3, 0xE4;" : "=r"(d) : "r"(a), "r"(b), "r"(c));
    return d;
}
__device__ __forceinline__ u32 smem_u32(const void* p) {
    u32 a; asm("{ .reg .u64 t; cvta.to.shared.u64 t, %1; cvt.u32.u64 %0, t; }"
               : "=r"(a) : "l"(p));
    return a;
}
__device__ __forceinline__ void ldsm_x4(u32* r, u32 addr) {
    asm volatile("ldmatrix.sync.aligned.m8n8.x4.shared.b16 {%0,%1,%2,%3}, [%4];"
                 : "=r"(r[0]), "=r"(r[1]), "=r"(r[2]), "=r"(r[3]) : "r"(addr));
}
__device__ __forceinline__ void ldsm_x4t(u32* r, u32 addr) {
    asm volatile("ldmatrix.sync.aligned.m8n8.x4.trans.shared.b16 {%0,%1,%2,%3}, [%4];"
                 : "=r"(r[0]), "=r"(r[1]), "=r"(r[2]), "=r"(r[3]) : "r"(addr));
}
__device__ __forceinline__ void mma_f16(float* d, const u32* a, u32 b0, u32 b1) {
    asm volatile(
        "mma.sync.aligned.m16n8k16.row.col.f32.f16.f16.f32 "
        "{%0,%1,%2,%3}, {%4,%5,%6,%7}, {%8,%9}, {%0,%1,%2,%3};"
        : "+f"(d[0]), "+f"(d[1]), "+f"(d[2]), "+f"(d[3])
        : "r"(a[0]), "r"(a[1]), "r"(a[2]), "r"(a[3]), "r"(b0), "r"(b1));
}
__device__ __forceinline__ void cpa16(u32 dst, const void* src) {
    asm volatile("{ .reg .u64 g; cvta.to.global.u64 g, %1; "
                 "cp.async.cg.shared.global [%0], [g], 16; }"
                 :: "r"(dst), "l"(src) : "memory");
}

// ---------------------------------------------------------------------------
// k_u: u1 = W @ a1, u2 = W @ a2.
// ---------------------------------------------------------------------------
__global__ __launch_bounds__(256) void k_u(const float* __restrict__ W,
                                           const float* __restrict__ avec) {
    int k = blockIdx.x * 8 + (threadIdx.x >> 5);
    int lane = threadIdx.x & 31;
    const float* wr = W + (size_t)k * FD;
    float s1 = 0.f, s2 = 0.f;
    #pragma unroll
    for (int q = 0; q < 4; q++) {
        int f4 = lane + 32 * q;
        float4 w = *(const float4*)&wr[f4 * 4];
        float4 a1 = *(const float4*)&avec[f4 * 4];
        float4 a2 = *(const float4*)&avec[FD + f4 * 4];
        s1 += w.x * a1.x + w.y * a1.y + w.z * a1.z + w.w * a1.w;
        s2 += w.x * a2.x + w.y * a2.y + w.z * a2.z + w.w * a2.w;
    }
    #pragma unroll
    for (int o = 16; o > 0; o >>= 1) {
        s1 += __shfl_xor_sync(0xffffffffu, s1, o);
        s2 += __shfl_xor_sync(0xffffffffu, s2, o);
    }
    if (lane == 0) { g_uvec[k] = s1; g_uvec[FD + k] = s2; }
}

// ---------------------------------------------------------------------------
// k_w12: w1/w2 exact fp32 via associativity.
// ---------------------------------------------------------------------------
__global__ __launch_bounds__(256) void k_w12(const float* __restrict__ xa,
                                             const float* __restrict__ xv) {
    int row  = blockIdx.x * 8 + (threadIdx.x >> 5);
    int lane = threadIdx.x & 31;
    int b = row >> 11, r = row & (T2 - 1);
    const float* h = (r < TT) ? xa + ((size_t)b * TT + r) * FD
                              : xv + ((size_t)b * TT + (r - TT)) * FD;
    float s1 = 0.f, s2 = 0.f;
    #pragma unroll
    for (int q = 0; q < 4; q++) {
        int f4 = lane + 32 * q;
        float4 v  = *(const float4*)&h[f4 * 4];
        float4 a1 = *(const float4*)&g_uvec[f4 * 4];
        float4 a2 = *(const float4*)&g_uvec[FD + f4 * 4];
        s1 += v.x * a1.x + v.y * a1.y + v.z * a1.z + v.w * a1.w;
        s2 += v.x * a2.x + v.y * a2.y + v.z * a2.z + v.w * a2.w;
    }
    #pragma unroll
    for (int o = 16; o > 0; o >>= 1) {
        s1 += __shfl_xor_sync(0xffffffffu, s1, o);
        s2 += __shfl_xor_sync(0xffffffffu, s2, o);
    }
    if (lane == 0) { g_w1[row] = s1; g_w2[row] = s2; }
}

// ---------------------------------------------------------------------------
// k_prep: max-shifted fp16 tables (all values <= 1, overflow-safe).
// ---------------------------------------------------------------------------
__global__ __launch_bounds__(256) void k_prep() {
    __shared__ float red[256];
    __shared__ float Msh;
    int b = blockIdx.x, tid = threadIdx.x;
    const float* w2 = g_w2 + b * T2;
    float m = -1e30f;
    for (int i = tid; i < T2; i += 256) m = fmaxf(m, w2[i]);
    red[tid] = m; __syncthreads();
    for (int s = 128; s > 0; s >>= 1) {
        if (tid < s) red[tid] = fmaxf(red[tid], red[tid + s]);
        __syncthreads();
    }
    if (tid == 0) Msh = red[0];
    __syncthreads();
    float M = Msh;
    for (int j2 = tid; j2 < T2 / 2; j2 += 256) {
        int j = 2 * j2;
        float w2a = w2[j], w2b = w2[j + 1];
        float e1a = expf(w2a - M), e1b = expf(w2b - M);
        float eaa = expf(ALPHA * (w2a - M)), eab = expf(ALPHA * (w2b - M));
        g_tbl[(size_t)b * (T2 / 2) + j2] =
            make_uint4(packhf(w2a, w2b), packhf(e1a, e1b), packhf(eaa, eab), 0);
    }
    const float* w1 = g_w1 + b * T2;
    for (int i = tid; i < T2; i += 256) {
        float v1 = w1[i];
        float s  = v1 + M;
        float mi = s > 0.f ? s : ALPHA * s;
        g_F1[b * T2 + i] = expf(s - mi);
        g_Fa[b * T2 + i] = expf(ALPHA * s - mi);
    }
}

// ---------------------------------------------------------------------------
// k_p: P fp16 [b][i][j] + exact fp32 row sums Z. Block = one row.
// Reads adj directly (mask computed inline; no separate pack pass).
// ---------------------------------------------------------------------------
__global__ __launch_bounds__(256) void k_p(const int* __restrict__ adj) {
    __shared__ float red[8];
    const int row = blockIdx.x;          // b*T2 + i
    const int b = row >> 11;
    const int t = threadIdx.x;
    const int lane = t & 31, wid = t >> 5;

    const float w1f = g_w1[row];
    const float f1f = g_F1[row], faf = g_Fa[row];
    const u32 w1h2 = packhf(w1f, w1f);
    const u32 F1h2 = packhf(f1f, f1f);
    const u32 Fah2 = packhf(faf, faf);

    const int* arow = adj + (size_t)row * T2 + t * 8;
    int4 a0 = *(const int4*)(arow);
    int4 a1 = *(const int4*)(arow + 4);
    int msk[8] = {a0.x, a0.y, a0.z, a0.w, a1.x, a1.y, a1.z, a1.w};
    const uint4* tb = g_tbl + (size_t)b * (T2 / 2) + t * 4;

    u32 hw[4];
    float zs = 0.f;
    #pragma unroll
    for (int e2 = 0; e2 < 4; e2++) {
        uint4 tt = tb[e2];
        u32 s = hadd2u(w1h2, tt.x);
        u32 m = hsetgt2(s, 0u);
        u32 e = lop3e4(tt.y, tt.z, m);
        u32 f = lop3e4(F1h2, Fah2, m);
        u32 p = hmul2u(f, e);
        u32 am = ((msk[e2 * 2] > 0 ? 1u : 0u) * 0xFFFFu)
               | ((msk[e2 * 2 + 1] > 0 ? 1u : 0u) * 0xFFFF0000u);
        p &= am;
        hw[e2] = p;
        float2 pf = __half22float2(*reinterpret_cast<__half2*>(&p));
        zs += pf.x + pf.y;
    }
    *(uint4*)&g_P[(size_t)row * T2 + t * 8] = make_uint4(hw[0], hw[1], hw[2], hw[3]);

    #pragma unroll
    for (int o = 16; o > 0; o >>= 1) zs += __shfl_xor_sync(0xffffffffu, zs, o);
    if (lane == 0) red[wid] = zs;
    __syncthreads();
    if (t == 0) {
        float z = 0.f;
        #pragma unroll
        for (int w = 0; w < 8; w++) z += red[w];
        g_Z[row] = z;
    }
}

// ---------------------------------------------------------------------------
// k_wh_mma: Wh = fl16(h) @ fl16(W), single fp16 pass. (validated)
// ---------------------------------------------------------------------------
#define WA_RB 144
#define WW_RB 272
#define SW_A 0
#define SW_W 18432
#define SW_TOTAL 35840

__global__ __launch_bounds__(256, 2) void k_wh_mma(const float* __restrict__ xa,
                                                   const float* __restrict__ xv,
                                                   const float* __restrict__ W) {
    extern __shared__ char sm[];
    const u32 smb = smem_u32(sm);
    const int tid = threadIdx.x, lane = tid & 31, wid = tid >> 5;
    const int wm = wid & 3, wn = wid >> 2;
    const int b  = blockIdx.z;
    const int r0 = blockIdx.y * 128;
    const int f0 = blockIdx.x * 128;
    const float* __restrict__ h = (r0 < TT)
        ? (xa + ((size_t)b * TT + r0) * FD)
        : (xv + ((size_t)b * TT + (r0 - TT)) * FD);

    float acc[2][8][4];
    #pragma unroll
    for (int m = 0; m < 2; m++)
        #pragma unroll
        for (int n = 0; n < 8; n++)
            #pragma unroll
            for (int e = 0; e < 4; e++) acc[m][n][e] = 0.f;

    const u32 a_lane = (u32)(lane & 15) * WA_RB + (u32)(lane >> 4) * 16;
    const u32 b_lane = (u32)(lane & 15) * WW_RB + (u32)(lane >> 4) * 16;
    const u32 pa = smb + SW_A + (u32)(wm * 32) * WA_RB + a_lane;
    const u32 pb = smb + SW_W + (u32)(wn * 64) * 2 + b_lane;

    for (int k0 = 0; k0 < FD; k0 += KC) {
        if (k0) __syncthreads();
        #pragma unroll
        for (int s = 0; s < 8; s++) {
            int u = tid + 256 * s;
            int row = u >> 4, kq = u & 15;
            float4 v = *(const float4*)(h + (size_t)row * FD + k0 + kq * 4);
            uint2 qh = make_uint2(packhf(v.x, v.y), packhf(v.z, v.w));
            *(uint2*)(sm + SW_A + row * WA_RB + kq * 8) = qh;
        }
        #pragma unroll
        for (int s = 0; s < 8; s++) {
            int u = tid + 256 * s;
            int row = u >> 5, fq = u & 31;
            float4 v = *(const float4*)(W + (size_t)(k0 + row) * FD + f0 + fq * 4);
            uint2 qh = make_uint2(packhf(v.x, v.y), packhf(v.z, v.w));
            *(uint2*)(sm + SW_W + row * WW_RB + fq * 8) = qh;
        }
        __syncthreads();
        #pragma unroll
        for (int kk = 0; kk < 4; kk++) {
            u32 ahi[2][4];
            ldsm_x4(ahi[0], pa + kk * 32);
            ldsm_x4(ahi[1], pa + kk * 32 + 16 * WA_RB);
            #pragma unroll
            for (int nt = 0; nt < 4; nt++) {
                u32 bhv[4];
                ldsm_x4t(bhv, pb + (u32)kk * 16 * WW_RB + (u32)nt * 32);
                #pragma unroll
                for (int mt = 0; mt < 2; mt++) {
                    mma_f16(acc[mt][2 * nt],     ahi[mt], bhv[0], bhv[1]);
                    mma_f16(acc[mt][2 * nt + 1], ahi[mt], bhv[2], bhv[3]);
                }
            }
        }
    }

    #pragma unroll
    for (int mt = 0; mt < 2; mt++) {
        int row1 = r0 + wm * 32 + mt * 16 + (lane >> 2);
        #pragma unroll
        for (int nt2 = 0; nt2 < 8; nt2++) {
            int col = f0 + wn * 64 + nt2 * 8 + (lane & 3) * 2;
            u32 h01 = packhf(acc[mt][nt2][0], acc[mt][nt2][1]);
            u32 h23 = packhf(acc[mt][nt2][2], acc[mt][nt2][3]);
            size_t o1 = ((size_t)b * T2 + row1) * FD + col;
            size_t o2 = o1 + (size_t)8 * FD;
            *(u32*)&g_B[o1] = h01;
            *(u32*)&g_B[o2] = h23;
        }
    }
}

// ---------------------------------------------------------------------------
// k_attn_mma: pure staged GEMM (R13 config). 128x128 tile, 256 thr, 2 CTA/SM,
// 3-deep cp.async pipeline. Grid: f-blocks fastest for L2 P reuse.
// ---------------------------------------------------------------------------
#define WHS_RB   272                // 128 f x 2B + 16 pad
#define PS_RB    144                // 64 j x 2B + 16 pad
#define WHS_BUF  17408              // 64 rows x 272
#define PS_BUF   18432              // 128 rows x 144
#define SM_PS    52224              // 3 * WHS_BUF
#define SM_ATTN_TOTAL 107520        // SM_PS + 3*PS_BUF

__device__ __forceinline__ void stage_tiles(u32 smb, int bsel,
                                            const __half* bh, const __half* prow,
                                            int j0, int f0, int tid) {
    u32 wbase = smb + (u32)bsel * WHS_BUF;
    #pragma unroll
    for (int s = 0; s < 4; s++) {
        int u = tid + 256 * s;
        int row = u >> 4, fo = u & 15;
        cpa16(wbase + row * WHS_RB + fo * 16,
              bh + (size_t)(j0 + row) * FD + f0 + fo * 8);
    }
    u32 pbase = smb + SM_PS + (u32)bsel * PS_BUF;
    #pragma unroll
    for (int s = 0; s < 4; s++) {
        int u = tid + 256 * s;
        int row = u >> 3, jo = u & 7;
        cpa16(pbase + row * PS_RB + jo * 16,
              prow + (size_t)row * T2 + j0 + jo * 8);
    }
    asm volatile("cp.async.commit_group;" ::: "memory");
}

__global__ __launch_bounds__(256, 2) void k_attn_mma(float* __restrict__ out) {
    extern __shared__ char sm[];
    const u32 smb = smem_u32(sm);
    const int tid = threadIdx.x;
    const int lane = tid & 31, wid = tid >> 5;
    const int wm = wid & 3, wn = wid >> 2;   // 4 x 2 warp grid
    const int b  = blockIdx.z;
    const int f0 = blockIdx.x * NF;          // f fastest -> L2 P reuse
    const int i0 = blockIdx.y * MI;

    const __half* bhsrc = g_B + (size_t)b * T2 * FD;
    const __half* prow  = g_P + ((size_t)(b * T2 + i0)) * T2;

    stage_tiles(smb, 0, bhsrc, prow, 0, f0, tid);
    stage_tiles(smb, 1, bhsrc, prow, KC, f0, tid);

    float acc[2][8][4];
    #pragma unroll
    for (int m = 0; m < 2; m++)
        #pragma unroll
        for (int n = 0; n < 8; n++)
            #pragma unroll
            for (int e = 0; e < 4; e++) acc[m][n][e] = 0.f;

    const u32 a_lane = (u32)(lane & 15) * PS_RB + (u32)(lane >> 4) * 16;
    const u32 b_lane = (u32)(lane & 15) * WHS_RB + (u32)(lane >> 4) * 16;
    const u32 pa_base = smb + SM_PS + (u32)(wm * 32) * PS_RB + a_lane;

    asm volatile("cp.async.wait_group 1;" ::: "memory");
    __syncthreads();

    for (int c = 0; c < NCHUNK; c++) {
        if (c + 2 < NCHUNK)
            stage_tiles(smb, (c + 2) % 3, bhsrc, prow, (c + 2) * KC, f0, tid);

        const u32 pa = pa_base + (u32)(c % 3) * PS_BUF;
        const u32 wb = smb + (u32)(c % 3) * WHS_BUF + (u32)(wn * 64) * 2 + b_lane;
        #pragma unroll
        for (int kk = 0; kk < 4; kk++) {
            u32 ap_[2][4];
            ldsm_x4(ap_[0], pa + kk * 32);
            ldsm_x4(ap_[1], pa + kk * 32 + 16 * PS_RB);
            #pragma unroll
            for (int nt = 0; nt < 4; nt++) {
                u32 bhv[4];
                ldsm_x4t(bhv, wb + (u32)kk * 16 * WHS_RB + (u32)nt * 32);
                #pragma unroll
                for (int mt = 0; mt < 2; mt++) {
                    mma_f16(acc[mt][2 * nt],     ap_[mt], bhv[0], bhv[1]);
                    mma_f16(acc[mt][2 * nt + 1], ap_[mt], bhv[2], bhv[3]);
                }
            }
        }

        if (c + 2 < NCHUNK)
            asm volatile("cp.async.wait_group 1;" ::: "memory");
        else
            asm volatile("cp.async.wait_group 0;" ::: "memory");
        __syncthreads();
    }

    // epilogue: normalize (Z from g_Z), elu, split-write
    #pragma unroll
    for (int mt = 0; mt < 2; mt++) {
        int il = wm * 32 + mt * 16 + (lane >> 2);
        int g1 = i0 + il, g2 = g1 + 8;
        float inv1 = 1.f / g_Z[b * T2 + g1];
        float inv2 = 1.f / g_Z[b * T2 + g2];
        size_t base1 = (g1 < TT) ? ((size_t)b * TT + g1) * FD
                                 : ((size_t)BS * TT + (size_t)b * TT + (g1 - TT)) * FD;
        size_t base2 = (g2 < TT) ? ((size_t)b * TT + g2) * FD
                                 : ((size_t)BS * TT + (size_t)b * TT + (g2 - TT)) * FD;
        #pragma unroll
        for (int nt = 0; nt < 8; nt++) {
            int col = f0 + wn * 64 + nt * 8 + (lane & 3) * 2;
            float2 v1, v2;
            float x;
            x = acc[mt][nt][0] * inv1; v1.x = x > 0.f ? x : expm1f(x);
            x = acc[mt][nt][1] * inv1; v1.y = x > 0.f ? x : expm1f(x);
            x = acc[mt][nt][2] * inv2; v2.x = x > 0.f ? x : expm1f(x);
            x = acc[mt][nt][3] * inv2; v2.y = x > 0.f ? x : expm1f(x);
            *(float2*)&out[base1 + col] = v1;
            *(float2*)&out[base2 + col] = v2;
        }
    }
}

// ---------------------------------------------------------------------------
extern "C" void kernel_launch(void* const* d_in, const int* in_sizes, int n_in,
                              void* d_out, int out_size) {
    const float* xa  = (const float*)d_in[0];
    const float* xv  = (const float*)d_in[1];
    const int*   adj = (const int*)d_in[2];
    const float* W   = (const float*)d_in[3];
    const float* a   = (const float*)d_in[4];
    float* out = (float*)d_out;

    cudaFuncSetAttribute(k_wh_mma, cudaFuncAttributeMaxDynamicSharedMemorySize,
                         SW_TOTAL);
    cudaFuncSetAttribute(k_attn_mma, cudaFuncAttributeMaxDynamicSharedMemorySize,
                         SM_ATTN_TOTAL);

    k_u<<<FD / 8, 256>>>(W, a);
    k_w12<<<BS * T2 / 8, 256>>>(xa, xv);
    k_prep<<<BS, 256>>>();
    k_p<<<BS * T2, 256>>>(adj);              // 32768 blocks, one row each
    dim3 gA(FD / 128, T2 / 128, BS);
    k_wh_mma<<<gA, 256, SW_TOTAL>>>(xa, xv, W);
    dim3 gC(FD / NF, T2 / MI, BS);           // 4 x 16 x 16 = 1024 blocks
    k_attn_mma<<<gC, 256, SM_ATTN_TOTAL>>>(out);
}

// round 16
// speedup vs baseline: 1.2547x; 1.0471x over previous
#include <cuda_runtime.h>
#include <cuda_fp16.h>
#include <math.h>
#include <stdint.h>

#define BS 16
#define TT 1024
#define T2 2048
#define FD 512
#define ALPHA 0.1f
#define KC 64
#define NCHUNK (T2 / KC)   // 32
#define MI 128
#define NF 128

typedef unsigned long long u64;
typedef unsigned int u32;

// ---------------- device scratch (no cudaMalloc allowed) --------------------
static __device__ __half g_B[(size_t)BS * T2 * FD];        // Wh fp16 [b][j][f]
static __device__ __half g_P[(size_t)BS * T2 * T2];        // P fp16 [b][i][j], 128MB
static __device__ float g_Z[BS * T2];                      // softmax denominators
static __device__ uint4 g_tbl[(size_t)BS * (T2 / 2)];      // {w2h2,E1h2,Eah2,0}/2j
static __device__ float g_uvec[2 * FD];
static __device__ float g_w1[BS * T2];
static __device__ float g_w2[BS * T2];
static __device__ float g_F1[BS * T2];
static __device__ float g_Fa[BS * T2];

// ---------------- helpers ----------------------------------------------------
__device__ __forceinline__ u32 packhf(float lo, float hi) {
    u32 r; asm("cvt.rn.f16x2.f32 %0, %1, %2;" : "=r"(r) : "f"(hi), "f"(lo)); return r;
}
__device__ __forceinline__ u32 hadd2u(u32 a, u32 b) {
    u32 d; asm("add.rn.f16x2 %0, %1, %2;" : "=r"(d) : "r"(a), "r"(b)); return d;
}
__device__ __forceinline__ u32 hmul2u(u32 a, u32 b) {
    u32 d; asm("mul.rn.f16x2 %0, %1, %2;" : "=r"(d) : "r"(a), "r"(b)); return d;
}
__device__ __forceinline__ u32 hsetgt2(u32 a, u32 b) {
    u32 d; asm("set.gt.u32.f16x2 %0, %1, %2;" : "=r"(d) : "r"(a), "r"(b)); return d;
}
// (a & c) | (b & ~c)
__device__ __forceinline__ u32 lop3e4(u32 a, u32 b, u32 c) {
    u32 d; asm("lop3.b32 %0, %1, %2, %3, 0xE4;" : "=r"(d) : "r"(a), "r"(b), "r"(c));
    return d;
}
__device__ __forceinline__ u32 smem_u32(const void* p) {
    u32 a; asm("{ .reg .u64 t; cvta.to.shared.u64 t, %1; cvt.u32.u64 %0, t; }"
               : "=r"(a) : "l"(p));
    return a;
}
__device__ __forceinline__ void ldsm_x4(u32* r, u32 addr) {
    asm volatile("ldmatrix.sync.aligned.m8n8.x4.shared.b16 {%0,%1,%2,%3}, [%4];"
                 : "=r"(r[0]), "=r"(r[1]), "=r"(r[2]), "=r"(r[3]) : "r"(addr));
}
__device__ __forceinline__ void ldsm_x4t(u32* r, u32 addr) {
    asm volatile("ldmatrix.sync.aligned.m8n8.x4.trans.shared.b16 {%0,%1,%2,%3}, [%4];"
                 : "=r"(r[0]), "=r"(r[1]), "=r"(r[2]), "=r"(r[3]) : "r"(addr));
}
__device__ __forceinline__ void mma_f16(float* d, const u32* a, u32 b0, u32 b1) {
    asm volatile(
        "mma.sync.aligned.m16n8k16.row.col.f32.f16.f16.f32 "
        "{%0,%1,%2,%3}, {%4,%5,%6,%7}, {%8,%9}, {%0,%1,%2,%3};"
        : "+f"(d[0]), "+f"(d[1]), "+f"(d[2]), "+f"(d[3])
        : "r"(a[0]), "r"(a[1]), "r"(a[2]), "r"(a[3]), "r"(b0), "r"(b1));
}
__device__ __forceinline__ void cpa16(u32 dst, const void* src) {
    asm volatile("{ .reg .u64 g; cvta.to.global.u64 g, %1; "
                 "cp.async.cg.shared.global [%0], [g], 16; }"
                 :: "r"(dst), "l"(src) : "memory");
}

// ---------------------------------------------------------------------------
// k_u: u1 = W @ a1, u2 = W @ a2.
// ---------------------------------------------------------------------------
__global__ __launch_bounds__(256) void k_u(const float* __restrict__ W,
                                           const float* __restrict__ avec) {
    int k = blockIdx.x * 8 + (threadIdx.x >> 5);
    int lane = threadIdx.x & 31;
    const float* wr = W + (size_t)k * FD;
    float s1 = 0.f, s2 = 0.f;
    #pragma unroll
    for (int q = 0; q < 4; q++) {
        int f4 = lane + 32 * q;
        float4 w = *(const float4*)&wr[f4 * 4];
        float4 a1 = *(const float4*)&avec[f4 * 4];
        float4 a2 = *(const float4*)&avec[FD + f4 * 4];
        s1 += w.x * a1.x + w.y * a1.y + w.z * a1.z + w.w * a1.w;
        s2 += w.x * a2.x + w.y * a2.y + w.z * a2.z + w.w * a2.w;
    }
    #pragma unroll
    for (int o = 16; o > 0; o >>= 1) {
        s1 += __shfl_xor_sync(0xffffffffu, s1, o);
        s2 += __shfl_xor_sync(0xffffffffu, s2, o);
    }
    if (lane == 0) { g_uvec[k] = s1; g_uvec[FD + k] = s2; }
}

// ---------------------------------------------------------------------------
// k_w12: w1/w2 exact fp32 via associativity.
// ---------------------------------------------------------------------------
__global__ __launch_bounds__(256) void k_w12(const float* __restrict__ xa,
                                             const float* __restrict__ xv) {
    int row  = blockIdx.x * 8 + (threadIdx.x >> 5);
    int lane = threadIdx.x & 31;
    int b = row >> 11, r = row & (T2 - 1);
    const float* h = (r < TT) ? xa + ((size_t)b * TT + r) * FD
                              : xv + ((size_t)b * TT + (r - TT)) * FD;
    float s1 = 0.f, s2 = 0.f;
    #pragma unroll
    for (int q = 0; q < 4; q++) {
        int f4 = lane + 32 * q;
        float4 v  = *(const float4*)&h[f4 * 4];
        float4 a1 = *(const float4*)&g_uvec[f4 * 4];
        float4 a2 = *(const float4*)&g_uvec[FD + f4 * 4];
        s1 += v.x * a1.x + v.y * a1.y + v.z * a1.z + v.w * a1.w;
        s2 += v.x * a2.x + v.y * a2.y + v.z * a2.z + v.w * a2.w;
    }
    #pragma unroll
    for (int o = 16; o > 0; o >>= 1) {
        s1 += __shfl_xor_sync(0xffffffffu, s1, o);
        s2 += __shfl_xor_sync(0xffffffffu, s2, o);
    }
    if (lane == 0) { g_w1[row] = s1; g_w2[row] = s2; }
}

// ---------------------------------------------------------------------------
// k_prep: max-shifted fp16 tables (all values <= 1, overflow-safe).
// ---------------------------------------------------------------------------
__global__ __launch_bounds__(256) void k_prep() {
    __shared__ float red[256];
    __shared__ float Msh;
    int b = blockIdx.x, tid = threadIdx.x;
    const float* w2 = g_w2 + b * T2;
    float m = -1e30f;
    for (int i = tid; i < T2; i += 256) m = fmaxf(m, w2[i]);
    red[tid] = m; __syncthreads();
    for (int s = 128; s > 0; s >>= 1) {
        if (tid < s) red[tid] = fmaxf(red[tid], red[tid + s]);
        __syncthreads();
    }
    if (tid == 0) Msh = red[0];
    __syncthreads();
    float M = Msh;
    for (int j2 = tid; j2 < T2 / 2; j2 += 256) {
        int j = 2 * j2;
        float w2a = w2[j], w2b = w2[j + 1];
        float e1a = expf(w2a - M), e1b = expf(w2b - M);
        float eaa = expf(ALPHA * (w2a - M)), eab = expf(ALPHA * (w2b - M));
        g_tbl[(size_t)b * (T2 / 2) + j2] =
            make_uint4(packhf(w2a, w2b), packhf(e1a, e1b), packhf(eaa, eab), 0);
    }
    const float* w1 = g_w1 + b * T2;
    for (int i = tid; i < T2; i += 256) {
        float v1 = w1[i];
        float s  = v1 + M;
        float mi = s > 0.f ? s : ALPHA * s;
        g_F1[b * T2 + i] = expf(s - mi);
        g_Fa[b * T2 + i] = expf(ALPHA * s - mi);
    }
}

// ---------------------------------------------------------------------------
// k_p: P fp16 [b][i][j] + exact fp32 row sums Z. Block = one row.
// Coalesced mapping: thread t handles pair-indices j2 = t + e2*256, so every
// warp instruction is line-perfect (tbl 512B, adj 256B, P 128B contiguous).
// ---------------------------------------------------------------------------
__global__ __launch_bounds__(256) void k_p(const int* __restrict__ adj) {
    __shared__ float red[8];
    const int row = blockIdx.x;          // b*T2 + i
    const int b = row >> 11;
    const int t = threadIdx.x;
    const int lane = t & 31, wid = t >> 5;

    const float w1f = g_w1[row];
    const float f1f = g_F1[row], faf = g_Fa[row];
    const u32 w1h2 = packhf(w1f, w1f);
    const u32 F1h2 = packhf(f1f, f1f);
    const u32 Fah2 = packhf(faf, faf);

    const uint4* tb = g_tbl + (size_t)b * (T2 / 2) + t;
    const int* arow = adj + (size_t)row * T2;
    __half* prow = g_P + (size_t)row * T2;

    float zs = 0.f;
    #pragma unroll
    for (int e2 = 0; e2 < 4; e2++) {
        int j2 = t + e2 * 256;           // pair index, lane-contiguous
        uint4 tt = tb[e2 * 256];
        int2 av = *(const int2*)(arow + 2 * j2);
        u32 s = hadd2u(w1h2, tt.x);
        u32 m = hsetgt2(s, 0u);
        u32 e = lop3e4(tt.y, tt.z, m);
        u32 f = lop3e4(F1h2, Fah2, m);
        u32 p = hmul2u(f, e);
        u32 am = ((av.x > 0 ? 1u : 0u) * 0xFFFFu)
               | ((av.y > 0 ? 1u : 0u) * 0xFFFF0000u);
        p &= am;
        float2 pf = __half22float2(*reinterpret_cast<__half2*>(&p));
        zs += pf.x + pf.y;
        *(u32*)&prow[2 * j2] = p;
    }

    #pragma unroll
    for (int o = 16; o > 0; o >>= 1) zs += __shfl_xor_sync(0xffffffffu, zs, o);
    if (lane == 0) red[wid] = zs;
    __syncthreads();
    if (t == 0) {
        float z = 0.f;
        #pragma unroll
        for (int w = 0; w < 8; w++) z += red[w];
        g_Z[row] = z;
    }
}

// ---------------------------------------------------------------------------
// k_wh_mma: Wh = fl16(h) @ fl16(W), single fp16 pass. (validated)
// ---------------------------------------------------------------------------
#define WA_RB 144
#define WW_RB 272
#define SW_A 0
#define SW_W 18432
#define SW_TOTAL 35840

__global__ __launch_bounds__(256, 2) void k_wh_mma(const float* __restrict__ xa,
                                                   const float* __restrict__ xv,
                                                   const float* __restrict__ W) {
    extern __shared__ char sm[];
    const u32 smb = smem_u32(sm);
    const int tid = threadIdx.x, lane = tid & 31, wid = tid >> 5;
    const int wm = wid & 3, wn = wid >> 2;
    const int b  = blockIdx.z;
    const int r0 = blockIdx.y * 128;
    const int f0 = blockIdx.x * 128;
    const float* __restrict__ h = (r0 < TT)
        ? (xa + ((size_t)b * TT + r0) * FD)
        : (xv + ((size_t)b * TT + (r0 - TT)) * FD);

    float acc[2][8][4];
    #pragma unroll
    for (int m = 0; m < 2; m++)
        #pragma unroll
        for (int n = 0; n < 8; n++)
            #pragma unroll
            for (int e = 0; e < 4; e++) acc[m][n][e] = 0.f;

    const u32 a_lane = (u32)(lane & 15) * WA_RB + (u32)(lane >> 4) * 16;
    const u32 b_lane = (u32)(lane & 15) * WW_RB + (u32)(lane >> 4) * 16;
    const u32 pa = smb + SW_A + (u32)(wm * 32) * WA_RB + a_lane;
    const u32 pb = smb + SW_W + (u32)(wn * 64) * 2 + b_lane;

    for (int k0 = 0; k0 < FD; k0 += KC) {
        if (k0) __syncthreads();
        #pragma unroll
        for (int s = 0; s < 8; s++) {
            int u = tid + 256 * s;
            int row = u >> 4, kq = u & 15;
            float4 v = *(const float4*)(h + (size_t)row * FD + k0 + kq * 4);
            uint2 qh = make_uint2(packhf(v.x, v.y), packhf(v.z, v.w));
            *(uint2*)(sm + SW_A + row * WA_RB + kq * 8) = qh;
        }
        #pragma unroll
        for (int s = 0; s < 8; s++) {
            int u = tid + 256 * s;
            int row = u >> 5, fq = u & 31;
            float4 v = *(const float4*)(W + (size_t)(k0 + row) * FD + f0 + fq * 4);
            uint2 qh = make_uint2(packhf(v.x, v.y), packhf(v.z, v.w));
            *(uint2*)(sm + SW_W + row * WW_RB + fq * 8) = qh;
        }
        __syncthreads();
        #pragma unroll
        for (int kk = 0; kk < 4; kk++) {
            u32 ahi[2][4];
            ldsm_x4(ahi[0], pa + kk * 32);
            ldsm_x4(ahi[1], pa + kk * 32 + 16 * WA_RB);
            #pragma unroll
            for (int nt = 0; nt < 4; nt++) {
                u32 bhv[4];
                ldsm_x4t(bhv, pb + (u32)kk * 16 * WW_RB + (u32)nt * 32);
                #pragma unroll
                for (int mt = 0; mt < 2; mt++) {
                    mma_f16(acc[mt][2 * nt],     ahi[mt], bhv[0], bhv[1]);
                    mma_f16(acc[mt][2 * nt + 1], ahi[mt], bhv[2], bhv[3]);
                }
            }
        }
    }

    #pragma unroll
    for (int mt = 0; mt < 2; mt++) {
        int row1 = r0 + wm * 32 + mt * 16 + (lane >> 2);
        #pragma unroll
        for (int nt2 = 0; nt2 < 8; nt2++) {
            int col = f0 + wn * 64 + nt2 * 8 + (lane & 3) * 2;
            u32 h01 = packhf(acc[mt][nt2][0], acc[mt][nt2][1]);
            u32 h23 = packhf(acc[mt][nt2][2], acc[mt][nt2][3]);
            size_t o1 = ((size_t)b * T2 + row1) * FD + col;
            size_t o2 = o1 + (size_t)8 * FD;
            *(u32*)&g_B[o1] = h01;
            *(u32*)&g_B[o2] = h23;
        }
    }
}

// ---------------------------------------------------------------------------
// k_attn_mma: pure staged GEMM (R13/R15 config). 128x128 tile, 256 thr,
// 2 CTA/SM, 3-deep cp.async pipeline. f-blocks fastest for L2 P reuse.
// ---------------------------------------------------------------------------
#define WHS_RB   272                // 128 f x 2B + 16 pad
#define PS_RB    144                // 64 j x 2B + 16 pad
#define WHS_BUF  17408              // 64 rows x 272
#define PS_BUF   18432              // 128 rows x 144
#define SM_PS    52224              // 3 * WHS_BUF
#define SM_ATTN_TOTAL 107520        // SM_PS + 3*PS_BUF

__device__ __forceinline__ void stage_tiles(u32 smb, int bsel,
                                            const __half* bh, const __half* prow,
                                            int j0, int f0, int tid) {
    u32 wbase = smb + (u32)bsel * WHS_BUF;
    #pragma unroll
    for (int s = 0; s < 4; s++) {
        int u = tid + 256 * s;
        int row = u >> 4, fo = u & 15;
        cpa16(wbase + row * WHS_RB + fo * 16,
              bh + (size_t)(j0 + row) * FD + f0 + fo * 8);
    }
    u32 pbase = smb + SM_PS + (u32)bsel * PS_BUF;
    #pragma unroll
    for (int s = 0; s < 4; s++) {
        int u = tid + 256 * s;
        int row = u >> 3, jo = u & 7;
        cpa16(pbase + row * PS_RB + jo * 16,
              prow + (size_t)row * T2 + j0 + jo * 8);
    }
    asm volatile("cp.async.commit_group;" ::: "memory");
}

__global__ __launch_bounds__(256, 2) void k_attn_mma(float* __restrict__ out) {
    extern __shared__ char sm[];
    const u32 smb = smem_u32(sm);
    const int tid = threadIdx.x;
    const int lane = tid & 31, wid = tid >> 5;
    const int wm = wid & 3, wn = wid >> 2;   // 4 x 2 warp grid
    const int b  = blockIdx.z;
    const int f0 = blockIdx.x * NF;          // f fastest -> L2 P reuse
    const int i0 = blockIdx.y * MI;

    const __half* bhsrc = g_B + (size_t)b * T2 * FD;
    const __half* prow  = g_P + ((size_t)(b * T2 + i0)) * T2;

    stage_tiles(smb, 0, bhsrc, prow, 0, f0, tid);
    stage_tiles(smb, 1, bhsrc, prow, KC, f0, tid);

    float acc[2][8][4];
    #pragma unroll
    for (int m = 0; m < 2; m++)
        #pragma unroll
        for (int n = 0; n < 8; n++)
            #pragma unroll
            for (int e = 0; e < 4; e++) acc[m][n][e] = 0.f;

    const u32 a_lane = (u32)(lane & 15) * PS_RB + (u32)(lane >> 4) * 16;
    const u32 b_lane = (u32)(lane & 15) * WHS_RB + (u32)(lane >> 4) * 16;
    const u32 pa_base = smb + SM_PS + (u32)(wm * 32) * PS_RB + a_lane;

    asm volatile("cp.async.wait_group 1;" ::: "memory");
    __syncthreads();

    for (int c = 0; c < NCHUNK; c++) {
        if (c + 2 < NCHUNK)
            stage_tiles(smb, (c + 2) % 3, bhsrc, prow, (c + 2) * KC, f0, tid);

        const u32 pa = pa_base + (u32)(c % 3) * PS_BUF;
        const u32 wb = smb + (u32)(c % 3) * WHS_BUF + (u32)(wn * 64) * 2 + b_lane;
        #pragma unroll
        for (int kk = 0; kk < 4; kk++) {
            u32 ap_[2][4];
            ldsm_x4(ap_[0], pa + kk * 32);
            ldsm_x4(ap_[1], pa + kk * 32 + 16 * PS_RB);
            #pragma unroll
            for (int nt = 0; nt < 4; nt++) {
                u32 bhv[4];
                ldsm_x4t(bhv, wb + (u32)kk * 16 * WHS_RB + (u32)nt * 32);
                #pragma unroll
                for (int mt = 0; mt < 2; mt++) {
                    mma_f16(acc[mt][2 * nt],     ap_[mt], bhv[0], bhv[1]);
                    mma_f16(acc[mt][2 * nt + 1], ap_[mt], bhv[2], bhv[3]);
                }
            }
        }

        if (c + 2 < NCHUNK)
            asm volatile("cp.async.wait_group 1;" ::: "memory");
        else
            asm volatile("cp.async.wait_group 0;" ::: "memory");
        __syncthreads();
    }

    // epilogue: normalize (Z from g_Z), elu, split-write
    #pragma unroll
    for (int mt = 0; mt < 2; mt++) {
        int il = wm * 32 + mt * 16 + (lane >> 2);
        int g1 = i0 + il, g2 = g1 + 8;
        float inv1 = 1.f / g_Z[b * T2 + g1];
        float inv2 = 1.f / g_Z[b * T2 + g2];
        size_t base1 = (g1 < TT) ? ((size_t)b * TT + g1) * FD
                                 : ((size_t)BS * TT + (size_t)b * TT + (g1 - TT)) * FD;
        size_t base2 = (g2 < TT) ? ((size_t)b * TT + g2) * FD
                                 : ((size_t)BS * TT + (size_t)b * TT + (g2 - TT)) * FD;
        #pragma unroll
        for (int nt = 0; nt < 8; nt++) {
            int col = f0 + wn * 64 + nt * 8 + (lane & 3) * 2;
            float2 v1, v2;
            float x;
            x = acc[mt][nt][0] * inv1; v1.x = x > 0.f ? x : expm1f(x);
            x = acc[mt][nt][1] * inv1; v1.y = x > 0.f ? x : expm1f(x);
            x = acc[mt][nt][2] * inv2; v2.x = x > 0.f ? x : expm1f(x);
            x = acc[mt][nt][3] * inv2; v2.y = x > 0.f ? x : expm1f(x);
            *(float2*)&out[base1 + col] = v1;
            *(float2*)&out[base2 + col] = v2;
        }
    }
}

// ---------------------------------------------------------------------------
extern "C" void kernel_launch(void* const* d_in, const int* in_sizes, int n_in,
                              void* d_out, int out_size) {
    const float* xa  = (const float*)d_in[0];
    const float* xv  = (const float*)d_in[1];
    const int*   adj = (const int*)d_in[2];
    const float* W   = (const float*)d_in[3];
    const float* a   = (const float*)d_in[4];
    float* out = (float*)d_out;

    cudaFuncSetAttribute(k_wh_mma, cudaFuncAttributeMaxDynamicSharedMemorySize,
                         SW_TOTAL);
    cudaFuncSetAttribute(k_attn_mma, cudaFuncAttributeMaxDynamicSharedMemorySize,
                         SM_ATTN_TOTAL);

    k_u<<<FD / 8, 256>>>(W, a);
    k_w12<<<BS * T2 / 8, 256>>>(xa, xv);
    k_prep<<<BS, 256>>>();
    k_p<<<BS * T2, 256>>>(adj);              // 32768 blocks, one row each
    dim3 gA(FD / 128, T2 / 128, BS);
    k_wh_mma<<<gA, 256, SW_TOTAL>>>(xa, xv, W);
    dim3 gC(FD / NF, T2 / MI, BS);           // 4 x 16 x 16 = 1024 blocks
    k_attn_mma<<<gC, 256, SM_ATTN_TOTAL>>>(out);
}

// round 17
// speedup vs baseline: 1.3167x; 1.0494x over previous
#include <cuda_runtime.h>
#include <cuda_fp16.h>
#include <math.h>
#include <stdint.h>

#define BS 16
#define TT 1024
#define T2 2048
#define FD 512
#define ALPHA 0.1f
#define KC 64
#define NCHUNK (T2 / KC)   // 32
#define MI 128
#define NF 128

typedef unsigned long long u64;
typedef unsigned int u32;

// ---------------- device scratch (no cudaMalloc allowed) --------------------
static __device__ __half g_B[(size_t)BS * T2 * FD];        // Wh fp16 [b][j][f]
static __device__ __half g_P[(size_t)BS * T2 * T2];        // P fp16 [b][i][j], 128MB
static __device__ float g_Z[BS * T2];                      // softmax denominators
static __device__ uint4 g_tbl[(size_t)BS * (T2 / 2)];      // {w2h2,E1h2,Eah2,0}/2j
static __device__ float g_uvec[2 * FD];
static __device__ float g_w1[BS * T2];
static __device__ float g_w2[BS * T2];
static __device__ float g_F1[BS * T2];
static __device__ float g_Fa[BS * T2];

// ---------------- helpers ----------------------------------------------------
__device__ __forceinline__ u32 packhf(float lo, float hi) {
    u32 r; asm("cvt.rn.f16x2.f32 %0, %1, %2;" : "=r"(r) : "f"(hi), "f"(lo)); return r;
}
__device__ __forceinline__ u32 hadd2u(u32 a, u32 b) {
    u32 d; asm("add.rn.f16x2 %0, %1, %2;" : "=r"(d) : "r"(a), "r"(b)); return d;
}
__device__ __forceinline__ u32 hmul2u(u32 a, u32 b) {
    u32 d; asm("mul.rn.f16x2 %0, %1, %2;" : "=r"(d) : "r"(a), "r"(b)); return d;
}
__device__ __forceinline__ u32 hsetgt2(u32 a, u32 b) {
    u32 d; asm("set.gt.u32.f16x2 %0, %1, %2;" : "=r"(d) : "r"(a), "r"(b)); return d;
}
// (a & c) | (b & ~c)
__device__ __forceinline__ u32 lop3e4(u32 a, u32 b, u32 c) {
    u32 d; asm("lop3.b32 %0, %1, %2, %3, 0xE4;" : "=r"(d) : "r"(a), "r"(b), "r"(c));
    return d;
}
__device__ __forceinline__ u32 smem_u32(const void* p) {
    u32 a; asm("{ .reg .u64 t; cvta.to.shared.u64 t, %1; cvt.u32.u64 %0, t; }"
               : "=r"(a) : "l"(p));
    return a;
}
__device__ __forceinline__ void ldsm_x4(u32* r, u32 addr) {
    asm volatile("ldmatrix.sync.aligned.m8n8.x4.shared.b16 {%0,%1,%2,%3}, [%4];"
                 : "=r"(r[0]), "=r"(r[1]), "=r"(r[2]), "=r"(r[3]) : "r"(addr));
}
__device__ __forceinline__ void ldsm_x4t(u32* r, u32 addr) {
    asm volatile("ldmatrix.sync.aligned.m8n8.x4.trans.shared.b16 {%0,%1,%2,%3}, [%4];"
                 : "=r"(r[0]), "=r"(r[1]), "=r"(r[2]), "=r"(r[3]) : "r"(addr));
}
__device__ __forceinline__ void mma_f16(float* d, const u32* a, u32 b0, u32 b1) {
    asm volatile(
        "mma.sync.aligned.m16n8k16.row.col.f32.f16.f16.f32 "
        "{%0,%1,%2,%3}, {%4,%5,%6,%7}, {%8,%9}, {%0,%1,%2,%3};"
        : "+f"(d[0]), "+f"(d[1]), "+f"(d[2]), "+f"(d[3])
        : "r"(a[0]), "r"(a[1]), "r"(a[2]), "r"(a[3]), "r"(b0), "r"(b1));
}
__device__ __forceinline__ void cpa16(u32 dst, const void* src) {
    asm volatile("{ .reg .u64 g; cvta.to.global.u64 g, %1; "
                 "cp.async.cg.shared.global [%0], [g], 16; }"
                 :: "r"(dst), "l"(src) : "memory");
}

// ---------------------------------------------------------------------------
// k_u: u1 = W @ a1, u2 = W @ a2.
// ---------------------------------------------------------------------------
__global__ __launch_bounds__(256) void k_u(const float* __restrict__ W,
                                           const float* __restrict__ avec) {
    int k = blockIdx.x * 8 + (threadIdx.x >> 5);
    int lane = threadIdx.x & 31;
    const float* wr = W + (size_t)k * FD;
    float s1 = 0.f, s2 = 0.f;
    #pragma unroll
    for (int q = 0; q < 4; q++) {
        int f4 = lane + 32 * q;
        float4 w = *(const float4*)&wr[f4 * 4];
        float4 a1 = *(const float4*)&avec[f4 * 4];
        float4 a2 = *(const float4*)&avec[FD + f4 * 4];
        s1 += w.x * a1.x + w.y * a1.y + w.z * a1.z + w.w * a1.w;
        s2 += w.x * a2.x + w.y * a2.y + w.z * a2.z + w.w * a2.w;
    }
    #pragma unroll
    for (int o = 16; o > 0; o >>= 1) {
        s1 += __shfl_xor_sync(0xffffffffu, s1, o);
        s2 += __shfl_xor_sync(0xffffffffu, s2, o);
    }
    if (lane == 0) { g_uvec[k] = s1; g_uvec[FD + k] = s2; }
}

// ---------------------------------------------------------------------------
// k_w12: w1/w2 exact fp32 via associativity.
// ---------------------------------------------------------------------------
__global__ __launch_bounds__(256) void k_w12(const float* __restrict__ xa,
                                             const float* __restrict__ xv) {
    int row  = blockIdx.x * 8 + (threadIdx.x >> 5);
    int lane = threadIdx.x & 31;
    int b = row >> 11, r = row & (T2 - 1);
    const float* h = (r < TT) ? xa + ((size_t)b * TT + r) * FD
                              : xv + ((size_t)b * TT + (r - TT)) * FD;
    float s1 = 0.f, s2 = 0.f;
    #pragma unroll
    for (int q = 0; q < 4; q++) {
        int f4 = lane + 32 * q;
        float4 v  = *(const float4*)&h[f4 * 4];
        float4 a1 = *(const float4*)&g_uvec[f4 * 4];
        float4 a2 = *(const float4*)&g_uvec[FD + f4 * 4];
        s1 += v.x * a1.x + v.y * a1.y + v.z * a1.z + v.w * a1.w;
        s2 += v.x * a2.x + v.y * a2.y + v.z * a2.z + v.w * a2.w;
    }
    #pragma unroll
    for (int o = 16; o > 0; o >>= 1) {
        s1 += __shfl_xor_sync(0xffffffffu, s1, o);
        s2 += __shfl_xor_sync(0xffffffffu, s2, o);
    }
    if (lane == 0) { g_w1[row] = s1; g_w2[row] = s2; }
}

// ---------------------------------------------------------------------------
// k_prep: max-shifted fp16 tables (all values <= 1, overflow-safe).
// ---------------------------------------------------------------------------
__global__ __launch_bounds__(256) void k_prep() {
    __shared__ float red[256];
    __shared__ float Msh;
    int b = blockIdx.x, tid = threadIdx.x;
    const float* w2 = g_w2 + b * T2;
    float m = -1e30f;
    for (int i = tid; i < T2; i += 256) m = fmaxf(m, w2[i]);
    red[tid] = m; __syncthreads();
    for (int s = 128; s > 0; s >>= 1) {
        if (tid < s) red[tid] = fmaxf(red[tid], red[tid + s]);
        __syncthreads();
    }
    if (tid == 0) Msh = red[0];
    __syncthreads();
    float M = Msh;
    for (int j2 = tid; j2 < T2 / 2; j2 += 256) {
        int j = 2 * j2;
        float w2a = w2[j], w2b = w2[j + 1];
        float e1a = expf(w2a - M), e1b = expf(w2b - M);
        float eaa = expf(ALPHA * (w2a - M)), eab = expf(ALPHA * (w2b - M));
        g_tbl[(size_t)b * (T2 / 2) + j2] =
            make_uint4(packhf(w2a, w2b), packhf(e1a, e1b), packhf(eaa, eab), 0);
    }
    const float* w1 = g_w1 + b * T2;
    for (int i = tid; i < T2; i += 256) {
        float v1 = w1[i];
        float s  = v1 + M;
        float mi = s > 0.f ? s : ALPHA * s;
        g_F1[b * T2 + i] = expf(s - mi);
        g_Fa[b * T2 + i] = expf(ALPHA * s - mi);
    }
}

// ---------------------------------------------------------------------------
// k_p: P fp16 [b][i][j] + exact fp32 row sums Z. Block = one row.
// Coalesced mapping: thread t handles pair-indices j2 = t + e2*256.
// ---------------------------------------------------------------------------
__global__ __launch_bounds__(256) void k_p(const int* __restrict__ adj) {
    __shared__ float red[8];
    const int row = blockIdx.x;          // b*T2 + i
    const int b = row >> 11;
    const int t = threadIdx.x;
    const int lane = t & 31, wid = t >> 5;

    const float w1f = g_w1[row];
    const float f1f = g_F1[row], faf = g_Fa[row];
    const u32 w1h2 = packhf(w1f, w1f);
    const u32 F1h2 = packhf(f1f, f1f);
    const u32 Fah2 = packhf(faf, faf);

    const uint4* tb = g_tbl + (size_t)b * (T2 / 2) + t;
    const int* arow = adj + (size_t)row * T2;
    __half* prow = g_P + (size_t)row * T2;

    float zs = 0.f;
    #pragma unroll
    for (int e2 = 0; e2 < 4; e2++) {
        int j2 = t + e2 * 256;           // pair index, lane-contiguous
        uint4 tt = tb[e2 * 256];
        int2 av = *(const int2*)(arow + 2 * j2);
        u32 s = hadd2u(w1h2, tt.x);
        u32 m = hsetgt2(s, 0u);
        u32 e = lop3e4(tt.y, tt.z, m);
        u32 f = lop3e4(F1h2, Fah2, m);
        u32 p = hmul2u(f, e);
        u32 am = ((av.x > 0 ? 1u : 0u) * 0xFFFFu)
               | ((av.y > 0 ? 1u : 0u) * 0xFFFF0000u);
        p &= am;
        float2 pf = __half22float2(*reinterpret_cast<__half2*>(&p));
        zs += pf.x + pf.y;
        *(u32*)&prow[2 * j2] = p;
    }

    #pragma unroll
    for (int o = 16; o > 0; o >>= 1) zs += __shfl_xor_sync(0xffffffffu, zs, o);
    if (lane == 0) red[wid] = zs;
    __syncthreads();
    if (t == 0) {
        float z = 0.f;
        #pragma unroll
        for (int w = 0; w < 8; w++) z += red[w];
        g_Z[row] = z;
    }
}

// ---------------------------------------------------------------------------
// k_wh_mma: Wh = fl16(h) @ fl16(W), single fp16 pass. (validated)
// ---------------------------------------------------------------------------
#define WA_RB 144
#define WW_RB 272
#define SW_A 0
#define SW_W 18432
#define SW_TOTAL 35840

__global__ __launch_bounds__(256, 2) void k_wh_mma(const float* __restrict__ xa,
                                                   const float* __restrict__ xv,
                                                   const float* __restrict__ W) {
    extern __shared__ char sm[];
    const u32 smb = smem_u32(sm);
    const int tid = threadIdx.x, lane = tid & 31, wid = tid >> 5;
    const int wm = wid & 3, wn = wid >> 2;
    const int b  = blockIdx.z;
    const int r0 = blockIdx.y * 128;
    const int f0 = blockIdx.x * 128;
    const float* __restrict__ h = (r0 < TT)
        ? (xa + ((size_t)b * TT + r0) * FD)
        : (xv + ((size_t)b * TT + (r0 - TT)) * FD);

    float acc[2][8][4];
    #pragma unroll
    for (int m = 0; m < 2; m++)
        #pragma unroll
        for (int n = 0; n < 8; n++)
            #pragma unroll
            for (int e = 0; e < 4; e++) acc[m][n][e] = 0.f;

    const u32 a_lane = (u32)(lane & 15) * WA_RB + (u32)(lane >> 4) * 16;
    const u32 b_lane = (u32)(lane & 15) * WW_RB + (u32)(lane >> 4) * 16;
    const u32 pa = smb + SW_A + (u32)(wm * 32) * WA_RB + a_lane;
    const u32 pb = smb + SW_W + (u32)(wn * 64) * 2 + b_lane;

    for (int k0 = 0; k0 < FD; k0 += KC) {
        if (k0) __syncthreads();
        #pragma unroll
        for (int s = 0; s < 8; s++) {
            int u = tid + 256 * s;
            int row = u >> 4, kq = u & 15;
            float4 v = *(const float4*)(h + (size_t)row * FD + k0 + kq * 4);
            uint2 qh = make_uint2(packhf(v.x, v.y), packhf(v.z, v.w));
            *(uint2*)(sm + SW_A + row * WA_RB + kq * 8) = qh;
        }
        #pragma unroll
        for (int s = 0; s < 8; s++) {
            int u = tid + 256 * s;
            int row = u >> 5, fq = u & 31;
            float4 v = *(const float4*)(W + (size_t)(k0 + row) * FD + f0 + fq * 4);
            uint2 qh = make_uint2(packhf(v.x, v.y), packhf(v.z, v.w));
            *(uint2*)(sm + SW_W + row * WW_RB + fq * 8) = qh;
        }
        __syncthreads();
        #pragma unroll
        for (int kk = 0; kk < 4; kk++) {
            u32 ahi[2][4];
            ldsm_x4(ahi[0], pa + kk * 32);
            ldsm_x4(ahi[1], pa + kk * 32 + 16 * WA_RB);
            #pragma unroll
            for (int nt = 0; nt < 4; nt++) {
                u32 bhv[4];
                ldsm_x4t(bhv, pb + (u32)kk * 16 * WW_RB + (u32)nt * 32);
                #pragma unroll
                for (int mt = 0; mt < 2; mt++) {
                    mma_f16(acc[mt][2 * nt],     ahi[mt], bhv[0], bhv[1]);
                    mma_f16(acc[mt][2 * nt + 1], ahi[mt], bhv[2], bhv[3]);
                }
            }
        }
    }

    #pragma unroll
    for (int mt = 0; mt < 2; mt++) {
        int row1 = r0 + wm * 32 + mt * 16 + (lane >> 2);
        #pragma unroll
        for (int nt2 = 0; nt2 < 8; nt2++) {
            int col = f0 + wn * 64 + nt2 * 8 + (lane & 3) * 2;
            u32 h01 = packhf(acc[mt][nt2][0], acc[mt][nt2][1]);
            u32 h23 = packhf(acc[mt][nt2][2], acc[mt][nt2][3]);
            size_t o1 = ((size_t)b * T2 + row1) * FD + col;
            size_t o2 = o1 + (size_t)8 * FD;
            *(u32*)&g_B[o1] = h01;
            *(u32*)&g_B[o2] = h23;
        }
    }
}

// ---------------------------------------------------------------------------
// k_attn_mma: pure staged GEMM (validated 391us config). 128x128, 256 thr,
// 2 CTA/SM, 3-deep cp.async pipeline, f-blocks fastest.
// ---------------------------------------------------------------------------
#define WHS_RB   272                // 128 f x 2B + 16 pad
#define PS_RB    144                // 64 j x 2B + 16 pad
#define WHS_BUF  17408              // 64 rows x 272
#define PS_BUF   18432              // 128 rows x 144
#define SM_PS    52224              // 3 * WHS_BUF
#define SM_ATTN_TOTAL 107520        // SM_PS + 3*PS_BUF

__device__ __forceinline__ void stage_tiles(u32 smb, int bsel,
                                            const __half* bh, const __half* prow,
                                            int j0, int f0, int tid) {
    u32 wbase = smb + (u32)bsel * WHS_BUF;
    #pragma unroll
    for (int s = 0; s < 4; s++) {
        int u = tid + 256 * s;
        int row = u >> 4, fo = u & 15;
        cpa16(wbase + row * WHS_RB + fo * 16,
              bh + (size_t)(j0 + row) * FD + f0 + fo * 8);
    }
    u32 pbase = smb + SM_PS + (u32)bsel * PS_BUF;
    #pragma unroll
    for (int s = 0; s < 4; s++) {
        int u = tid + 256 * s;
        int row = u >> 3, jo = u & 7;
        cpa16(pbase + row * PS_RB + jo * 16,
              prow + (size_t)row * T2 + j0 + jo * 8);
    }
    asm volatile("cp.async.commit_group;" ::: "memory");
}

__global__ __launch_bounds__(256, 2) void k_attn_mma(float* __restrict__ out) {
    extern __shared__ char sm[];
    const u32 smb = smem_u32(sm);
    const int tid = threadIdx.x;
    const int lane = tid & 31, wid = tid >> 5;
    const int wm = wid & 3, wn = wid >> 2;   // 4 x 2 warp grid
    const int b  = blockIdx.z;
    const int f0 = blockIdx.x * NF;          // f fastest -> L2 P reuse
    const int i0 = blockIdx.y * MI;

    const __half* bhsrc = g_B + (size_t)b * T2 * FD;
    const __half* prow  = g_P + ((size_t)(b * T2 + i0)) * T2;

    stage_tiles(smb, 0, bhsrc, prow, 0, f0, tid);
    stage_tiles(smb, 1, bhsrc, prow, KC, f0, tid);

    float acc[2][8][4];
    #pragma unroll
    for (int m = 0; m < 2; m++)
        #pragma unroll
        for (int n = 0; n < 8; n++)
            #pragma unroll
            for (int e = 0; e < 4; e++) acc[m][n][e] = 0.f;

    const u32 a_lane = (u32)(lane & 15) * PS_RB + (u32)(lane >> 4) * 16;
    const u32 b_lane = (u32)(lane & 15) * WHS_RB + (u32)(lane >> 4) * 16;
    const u32 pa_base = smb + SM_PS + (u32)(wm * 32) * PS_RB + a_lane;

    asm volatile("cp.async.wait_group 1;" ::: "memory");
    __syncthreads();

    for (int c = 0; c < NCHUNK; c++) {
        if (c + 2 < NCHUNK)
            stage_tiles(smb, (c + 2) % 3, bhsrc, prow, (c + 2) * KC, f0, tid);

        const u32 pa = pa_base + (u32)(c % 3) * PS_BUF;
        const u32 wb = smb + (u32)(c % 3) * WHS_BUF + (u32)(wn * 64) * 2 + b_lane;
        #pragma unroll
        for (int kk = 0; kk < 4; kk++) {
            u32 ap_[2][4];
            ldsm_x4(ap_[0], pa + kk * 32);
            ldsm_x4(ap_[1], pa + kk * 32 + 16 * PS_RB);
            #pragma unroll
            for (int nt = 0; nt < 4; nt++) {
                u32 bhv[4];
                ldsm_x4t(bhv, wb + (u32)kk * 16 * WHS_RB + (u32)nt * 32);
                #pragma unroll
                for (int mt = 0; mt < 2; mt++) {
                    mma_f16(acc[mt][2 * nt],     ap_[mt], bhv[0], bhv[1]);
                    mma_f16(acc[mt][2 * nt + 1], ap_[mt], bhv[2], bhv[3]);
                }
            }
        }

        if (c + 2 < NCHUNK)
            asm volatile("cp.async.wait_group 1;" ::: "memory");
        else
            asm volatile("cp.async.wait_group 0;" ::: "memory");
        __syncthreads();
    }

    // epilogue: normalize (Z from g_Z), elu, split-write
    #pragma unroll
    for (int mt = 0; mt < 2; mt++) {
        int il = wm * 32 + mt * 16 + (lane >> 2);
        int g1 = i0 + il, g2 = g1 + 8;
        float inv1 = 1.f / g_Z[b * T2 + g1];
        float inv2 = 1.f / g_Z[b * T2 + g2];
        size_t base1 = (g1 < TT) ? ((size_t)b * TT + g1) * FD
                                 : ((size_t)BS * TT + (size_t)b * TT + (g1 - TT)) * FD;
        size_t base2 = (g2 < TT) ? ((size_t)b * TT + g2) * FD
                                 : ((size_t)BS * TT + (size_t)b * TT + (g2 - TT)) * FD;
        #pragma unroll
        for (int nt = 0; nt < 8; nt++) {
            int col = f0 + wn * 64 + nt * 8 + (lane & 3) * 2;
            float2 v1, v2;
            float x;
            x = acc[mt][nt][0] * inv1; v1.x = x > 0.f ? x : expm1f(x);
            x = acc[mt][nt][1] * inv1; v1.y = x > 0.f ? x : expm1f(x);
            x = acc[mt][nt][2] * inv2; v2.x = x > 0.f ? x : expm1f(x);
            x = acc[mt][nt][3] * inv2; v2.y = x > 0.f ? x : expm1f(x);
            *(float2*)&out[base1 + col] = v1;
            *(float2*)&out[base2 + col] = v2;
        }
    }
}

// ---------------------------------------------------------------------------
// Launch: fork k_wh_mma onto a side stream, concurrent with the P chain.
//   main:  k_u -> k_w12 -> k_prep -> k_p ──┐
//   side:  k_wh_mma ───────────────────────┴-> k_attn_mma
// ---------------------------------------------------------------------------
extern "C" void kernel_launch(void* const* d_in, const int* in_sizes, int n_in,
                              void* d_out, int out_size) {
    const float* xa  = (const float*)d_in[0];
    const float* xv  = (const float*)d_in[1];
    const int*   adj = (const int*)d_in[2];
    const float* W   = (const float*)d_in[3];
    const float* a   = (const float*)d_in[4];
    float* out = (float*)d_out;

    cudaFuncSetAttribute(k_wh_mma, cudaFuncAttributeMaxDynamicSharedMemorySize,
                         SW_TOTAL);
    cudaFuncSetAttribute(k_attn_mma, cudaFuncAttributeMaxDynamicSharedMemorySize,
                         SM_ATTN_TOTAL);

    cudaStream_t s1;
    cudaStreamCreateWithFlags(&s1, cudaStreamNonBlocking);
    cudaEvent_t e0, e1;
    cudaEventCreateWithFlags(&e0, cudaEventDisableTiming);
    cudaEventCreateWithFlags(&e1, cudaEventDisableTiming);

    // fork: side stream runs the (independent) Wh GEMM
    cudaEventRecord(e0, 0);
    cudaStreamWaitEvent(s1, e0, 0);
    dim3 gA(FD / 128, T2 / 128, BS);
    k_wh_mma<<<gA, 256, SW_TOTAL, s1>>>(xa, xv, W);
    cudaEventRecord(e1, s1);

    // main chain: attention-score pipeline
    k_u<<<FD / 8, 256>>>(W, a);
    k_w12<<<BS * T2 / 8, 256>>>(xa, xv);
    k_prep<<<BS, 256>>>();
    k_p<<<BS * T2, 256>>>(adj);              // 32768 blocks, one row each

    // join, then the big GEMM
    cudaStreamWaitEvent(0, e1, 0);
    dim3 gC(FD / NF, T2 / MI, BS);           // 4 x 16 x 16 = 1024 blocks
    k_attn_mma<<<gC, 256, SM_ATTN_TOTAL>>>(out);

    cudaEventDestroy(e0);
    cudaEventDestroy(e1);
    cudaStreamDestroy(s1);
}